// round 4
// baseline (speedup 1.0000x reference)
#include <cuda_runtime.h>
#include <cuda_bf16.h>
#include <cstdint>

// Problem constants
#define B_   1024
#define P_   24
#define H_   2048
#define K1_  4096   // H*R
#define N1_  2048   // H
#define K2_  2048
#define N2_  1024   // H/2
#define OUTP 4

// Scratch (allocation-free rule: __device__ globals)
__device__ float g_xr [(size_t)B_ * P_ * H_];    // x rounded to tf32   201MB
__device__ float g_w1r[(size_t)P_ * K1_ * N1_];  // W1 rounded          805MB
__device__ float g_w2r[(size_t)P_ * K2_ * N2_];  // W2 rounded          201MB
__device__ float g_h1 [(size_t)P_ * B_ * N1_];   // layer1 out (rounded)
__device__ float g_h2 [(size_t)P_ * B_ * N2_];   // layer2 out

// ---------------------------------------------------------------------------
// helpers
// ---------------------------------------------------------------------------
__device__ __forceinline__ uint32_t f2tf(float x) {
    uint32_t r;
    asm("cvt.rna.tf32.f32 %0, %1;" : "=r"(r) : "f"(x));
    return r;
}
__device__ __forceinline__ float rna_tf32(float x) {
    return __uint_as_float(f2tf(x));
}

__device__ __forceinline__ void mma_tf32(float* c, const uint32_t* a, const uint32_t* b) {
    asm volatile(
        "mma.sync.aligned.m16n8k8.row.col.f32.tf32.tf32.f32 "
        "{%0,%1,%2,%3}, {%4,%5,%6,%7}, {%8,%9}, {%0,%1,%2,%3};"
        : "+f"(c[0]), "+f"(c[1]), "+f"(c[2]), "+f"(c[3])
        : "r"(a[0]), "r"(a[1]), "r"(a[2]), "r"(a[3]), "r"(b[0]), "r"(b[1]));
}

__device__ __forceinline__ void cp_async16(uint32_t smem_addr, const void* gptr, int src_size) {
    asm volatile("cp.async.cg.shared.global [%0], [%1], 16, %2;"
                 :: "r"(smem_addr), "l"(gptr), "r"(src_size));
}
__device__ __forceinline__ void cp_commit() {
    asm volatile("cp.async.commit_group;" ::: "memory");
}
template <int N>
__device__ __forceinline__ void cp_wait() {
    asm volatile("cp.async.wait_group %0;" :: "n"(N) : "memory");
}

__device__ __forceinline__ float gelu_exact(float v) {
    return 0.5f * v * (1.0f + erff(v * 0.7071067811865476f));
}

// ---------------------------------------------------------------------------
// Prepass: elementwise tf32-RNA rounding (float4 streaming)
// ---------------------------------------------------------------------------
__global__ void round_kernel(const float* __restrict__ in, float* __restrict__ outp, size_t n4) {
    size_t i = (size_t)blockIdx.x * blockDim.x + threadIdx.x;
    size_t stride = (size_t)gridDim.x * blockDim.x;
    for (; i < n4; i += stride) {
        float4 v = ((const float4*)in)[i];
        v.x = rna_tf32(v.x); v.y = rna_tf32(v.y);
        v.z = rna_tf32(v.z); v.w = rna_tf32(v.w);
        ((float4*)outp)[i] = v;
    }
}

// ---------------------------------------------------------------------------
// Grouped GEMM + GELU,  CTA tile 128(m) x 256(n), BK=32, 4-stage cp.async.
// 512 threads = 16 warps: warpM = wid>>2 (4, x32 rows), warpN = wid&3 (4, x64).
// All operands pre-rounded to tf32 -> NO cvt in mainloop.
// MODE 0: A = windowed g_xr[B,P,H] (K=4096, C=g_h1, output tf32-rounded)
// MODE 1: A = g_h1 [p][b][k]       (K=2048, C=g_h2)
// W is [P][K][N] row-major (N contiguous). C[p][b][n] = gelu(A@W + bias).
// ---------------------------------------------------------------------------
#define BM 128
#define BN 256
#define BK 32
#define ASTR 36            // A smem row stride: bank = 4g + cc (conflict-free)
#define BSTR 264           // B smem row stride: bank = 8cc + g (conflict-free)
#define ASZ (BM * ASTR)    // 4608 floats / stage
#define BSZ (BK * BSTR)    // 8448 floats / stage
#define STG (ASZ + BSZ)    // 13056 floats
#define NSTG 4
#define SMEM_BYTES (NSTG * STG * 4)   // 208896

template <int MODE>
__global__ void __launch_bounds__(512, 1)
gemm_act_kernel(const float* __restrict__ A, const float* __restrict__ W,
                const float* __restrict__ bias, float* __restrict__ C,
                int K, int N) {
    extern __shared__ float smem[];

    const int p    = blockIdx.z;
    const int bm   = blockIdx.y;
    const int bn   = blockIdx.x;
    const int tid  = threadIdx.x;
    const int wid  = tid >> 5;
    const int lane = tid & 31;
    const int warpM = wid >> 2;    // 0..3 (32 rows each)
    const int warpN = wid & 3;     // 0..3 (64 cols each)
    const int g  = lane >> 2;      // 0..7
    const int cc = lane & 3;       // 0..3

    float acc[2][8][4];
#pragma unroll
    for (int mf = 0; mf < 2; mf++)
#pragma unroll
        for (int nf = 0; nf < 8; nf++)
#pragma unroll
            for (int i = 0; i < 4; i++) acc[mf][nf][i] = 0.f;

    const float* Wp = W + (size_t)p * K * N + (size_t)bn * BN;

    auto load_tiles = [&](int kt, int buf) {
        float* As = smem + buf * STG;
        float* Bs = As + ASZ;
        // A: 1024 x 16B chunks over 512 threads -> 2 each
#pragma unroll
        for (int i = 0; i < 2; i++) {
            int c  = tid + i * 512;
            int m  = c >> 3;
            int kl = (c & 7) * 4;
            int kg = kt * BK + kl;
            const float* ga;
            int sz = 16;
            if (MODE == 0) {
                int half = (kg >= H_) ? 1 : 0;
                int pp   = p + half;
                int kk   = kg - half * H_;
                if (pp >= P_) { pp = P_ - 1; sz = 0; }   // right-edge zero pad
                ga = A + ((size_t)(bm * BM + m) * P_ + pp) * H_ + kk;
            } else {
                ga = A + ((size_t)p * B_ + bm * BM + m) * (size_t)K + kg;
            }
            uint32_t sa = (uint32_t)__cvta_generic_to_shared(&As[m * ASTR + kl]);
            cp_async16(sa, ga, sz);
        }
        // B: 2048 x 16B chunks -> 4 each
#pragma unroll
        for (int i = 0; i < 4; i++) {
            int c  = tid + i * 512;
            int kb = c >> 6;              // 0..31
            int nb = (c & 63) * 4;        // 0..252
            const float* gb = Wp + (size_t)(kt * BK + kb) * N + nb;
            uint32_t sb = (uint32_t)__cvta_generic_to_shared(&Bs[kb * BSTR + nb]);
            cp_async16(sb, gb, 16);
        }
    };

    const int NKT = K / BK;
    load_tiles(0, 0); cp_commit();
    load_tiles(1, 1); cp_commit();
    load_tiles(2, 2); cp_commit();

    for (int kt = 0; kt < NKT; ++kt) {
        int buf = kt & 3;
        if (kt + 3 < NKT) {
            load_tiles(kt + 3, (kt + 3) & 3);   // target consumed at kt-1, safe
            cp_commit();
            cp_wait<3>();
        } else {
            cp_wait<0>();
        }
        __syncthreads();

        const float* As = smem + buf * STG;
        const float* Bs = As + ASZ;
#pragma unroll
        for (int ks = 0; ks < 4; ks++) {
            const int k0 = ks * 8;
            uint32_t a[2][4], b[8][2];
#pragma unroll
            for (int mf = 0; mf < 2; mf++) {
                int row = warpM * 32 + mf * 16 + g;
                a[mf][0] = __float_as_uint(As[row * ASTR + k0 + cc]);
                a[mf][1] = __float_as_uint(As[(row + 8) * ASTR + k0 + cc]);
                a[mf][2] = __float_as_uint(As[row * ASTR + k0 + 4 + cc]);
                a[mf][3] = __float_as_uint(As[(row + 8) * ASTR + k0 + 4 + cc]);
            }
#pragma unroll
            for (int nf = 0; nf < 8; nf++) {
                int col = warpN * 64 + nf * 8 + g;
                b[nf][0] = __float_as_uint(Bs[(k0 + cc) * BSTR + col]);
                b[nf][1] = __float_as_uint(Bs[(k0 + 4 + cc) * BSTR + col]);
            }
#pragma unroll
            for (int mf = 0; mf < 2; mf++)
#pragma unroll
                for (int nf = 0; nf < 8; nf++)
                    mma_tf32(acc[mf][nf], a[mf], b[nf]);
        }
        __syncthreads();
    }

    // Epilogue: bias + exact GELU (MODE0 rounds to tf32 for layer-2 A), float2 stores
    const float* brow = bias + (size_t)p * N;
#pragma unroll
    for (int mf = 0; mf < 2; mf++) {
        int row0 = bm * BM + warpM * 32 + mf * 16 + g;
        size_t base0 = ((size_t)p * B_ + row0) * (size_t)N;
        size_t base8 = base0 + (size_t)8 * N;
#pragma unroll
        for (int nf = 0; nf < 8; nf++) {
            int n = bn * BN + warpN * 64 + nf * 8 + cc * 2;
            float bv0 = __ldg(brow + n);
            float bv1 = __ldg(brow + n + 1);
            float v0 = gelu_exact(acc[mf][nf][0] + bv0);
            float v1 = gelu_exact(acc[mf][nf][1] + bv1);
            float v2 = gelu_exact(acc[mf][nf][2] + bv0);
            float v3 = gelu_exact(acc[mf][nf][3] + bv1);
            if (MODE == 0) {
                v0 = rna_tf32(v0); v1 = rna_tf32(v1);
                v2 = rna_tf32(v2); v3 = rna_tf32(v3);
            }
            *(float2*)(C + base0 + n) = make_float2(v0, v1);
            *(float2*)(C + base8 + n) = make_float2(v2, v3);
        }
    }
}

// ---------------------------------------------------------------------------
// Layer 3: out[b, p*4+o] = relu(sum_k h2[p][b][k] * W3[p][k][o] + b3[p][o])
// ---------------------------------------------------------------------------
__global__ void l3_kernel(const float* __restrict__ h2, const float* __restrict__ W3,
                          const float* __restrict__ b3, float* __restrict__ out) {
    int p = blockIdx.x, b = blockIdx.y;
    int tid = threadIdx.x;
    const float* hrow = h2 + ((size_t)p * B_ + b) * N2_;
    const float* w    = W3 + (size_t)p * N2_ * OUTP;

    float a0 = 0.f, a1 = 0.f, a2 = 0.f, a3 = 0.f;
    for (int k = tid; k < N2_; k += 128) {
        float hv = hrow[k];
        const float* wr = w + k * OUTP;
        a0 += hv * wr[0]; a1 += hv * wr[1]; a2 += hv * wr[2]; a3 += hv * wr[3];
    }
#pragma unroll
    for (int off = 16; off; off >>= 1) {
        a0 += __shfl_down_sync(0xffffffffu, a0, off);
        a1 += __shfl_down_sync(0xffffffffu, a1, off);
        a2 += __shfl_down_sync(0xffffffffu, a2, off);
        a3 += __shfl_down_sync(0xffffffffu, a3, off);
    }
    __shared__ float sred[4][4];
    int warp = tid >> 5, lane = tid & 31;
    if (lane == 0) {
        sred[warp][0] = a0; sred[warp][1] = a1; sred[warp][2] = a2; sred[warp][3] = a3;
    }
    __syncthreads();
    if (tid < 4) {
        float s = sred[0][tid] + sred[1][tid] + sred[2][tid] + sred[3][tid]
                + b3[p * OUTP + tid];
        out[(size_t)b * (P_ * OUTP) + p * OUTP + tid] = fmaxf(s, 0.f);
    }
}

// ---------------------------------------------------------------------------
extern "C" void kernel_launch(void* const* d_in, const int* in_sizes, int n_in,
                              void* d_out, int out_size) {
    const float* x  = (const float*)d_in[0];
    const float* W1 = (const float*)d_in[1];
    const float* b1 = (const float*)d_in[2];
    const float* W2 = (const float*)d_in[3];
    const float* b2 = (const float*)d_in[4];
    const float* W3 = (const float*)d_in[5];
    const float* b3 = (const float*)d_in[6];
    float* out = (float*)d_out;

    float *xr, *w1r, *w2r, *h1, *h2;
    cudaGetSymbolAddress((void**)&xr,  g_xr);
    cudaGetSymbolAddress((void**)&w1r, g_w1r);
    cudaGetSymbolAddress((void**)&w2r, g_w2r);
    cudaGetSymbolAddress((void**)&h1,  g_h1);
    cudaGetSymbolAddress((void**)&h2,  g_h2);

    cudaFuncSetAttribute(gemm_act_kernel<0>,
                         cudaFuncAttributeMaxDynamicSharedMemorySize, SMEM_BYTES);
    cudaFuncSetAttribute(gemm_act_kernel<1>,
                         cudaFuncAttributeMaxDynamicSharedMemorySize, SMEM_BYTES);

    // Prepass: round x, W1, W2 to tf32 (removes all cvt from GEMM mainloops)
    round_kernel<<<2048, 256>>>(x,  xr,  (size_t)B_ * P_ * H_ / 4);
    round_kernel<<<8192, 256>>>(W1, w1r, (size_t)P_ * K1_ * N1_ / 4);
    round_kernel<<<4096, 256>>>(W2, w2r, (size_t)P_ * K2_ * N2_ / 4);

    // Layer 1: [1024, 4096] @ [4096, 2048] per p, GELU
    gemm_act_kernel<0><<<dim3(N1_ / BN, B_ / BM, P_), 512, SMEM_BYTES>>>(
        xr, w1r, b1, h1, K1_, N1_);
    // Layer 2: [1024, 2048] @ [2048, 1024] per p, GELU
    gemm_act_kernel<1><<<dim3(N2_ / BN, B_ / BM, P_), 512, SMEM_BYTES>>>(
        h1, w2r, b2, h2, K2_, N2_);
    // Layer 3: tiny N=4 + ReLU
    l3_kernel<<<dim3(P_, B_), 128>>>(h2, W3, b3, out);
}

// round 5
// speedup vs baseline: 1.8227x; 1.8227x over previous
#include <cuda_runtime.h>
#include <cuda_fp16.h>
#include <cstdint>

// Problem constants
#define B_   1024
#define P_   24
#define H_   2048
#define K1_  4096   // H*R
#define N1_  2048   // H
#define K2_  2048
#define N2_  1024   // H/2
#define OUTP 4

// Scratch (allocation-free rule: __device__ globals)
__device__ __half g_xh [(size_t)B_ * P_ * H_];    // x   -> fp16   100MB
__device__ __half g_w1h[(size_t)P_ * K1_ * N1_];  // W1  -> fp16   402MB
__device__ __half g_w2h[(size_t)P_ * K2_ * N2_];  // W2  -> fp16   100MB
__device__ __half g_h1h[(size_t)P_ * B_ * N1_];   // layer1 out fp16
__device__ float  g_h2 [(size_t)P_ * B_ * N2_];   // layer2 out fp32

// ---------------------------------------------------------------------------
// helpers
// ---------------------------------------------------------------------------
__device__ __forceinline__ void mma_f16(float* c, const uint32_t* a, const uint32_t* b) {
    asm volatile(
        "mma.sync.aligned.m16n8k16.row.col.f32.f16.f16.f32 "
        "{%0,%1,%2,%3}, {%4,%5,%6,%7}, {%8,%9}, {%0,%1,%2,%3};"
        : "+f"(c[0]), "+f"(c[1]), "+f"(c[2]), "+f"(c[3])
        : "r"(a[0]), "r"(a[1]), "r"(a[2]), "r"(a[3]), "r"(b[0]), "r"(b[1]));
}

__device__ __forceinline__ void ldsm4(uint32_t addr, uint32_t& r0, uint32_t& r1,
                                      uint32_t& r2, uint32_t& r3) {
    asm volatile("ldmatrix.sync.aligned.m8n8.x4.shared.b16 {%0,%1,%2,%3}, [%4];"
                 : "=r"(r0), "=r"(r1), "=r"(r2), "=r"(r3) : "r"(addr));
}
__device__ __forceinline__ void ldsm4t(uint32_t addr, uint32_t& r0, uint32_t& r1,
                                       uint32_t& r2, uint32_t& r3) {
    asm volatile("ldmatrix.sync.aligned.m8n8.x4.trans.shared.b16 {%0,%1,%2,%3}, [%4];"
                 : "=r"(r0), "=r"(r1), "=r"(r2), "=r"(r3) : "r"(addr));
}

__device__ __forceinline__ void cp_async16(uint32_t smem_addr, const void* gptr, int src_size) {
    asm volatile("cp.async.cg.shared.global [%0], [%1], 16, %2;"
                 :: "r"(smem_addr), "l"(gptr), "r"(src_size));
}
__device__ __forceinline__ void cp_commit() {
    asm volatile("cp.async.commit_group;" ::: "memory");
}
template <int N>
__device__ __forceinline__ void cp_wait() {
    asm volatile("cp.async.wait_group %0;" :: "n"(N) : "memory");
}

__device__ __forceinline__ float gelu_exact(float v) {
    return 0.5f * v * (1.0f + erff(v * 0.7071067811865476f));
}

// ---------------------------------------------------------------------------
// Prepass: fp32 -> fp16 (RN) streaming convert
// ---------------------------------------------------------------------------
__global__ void cvt_kernel(const float* __restrict__ in, __half* __restrict__ outp, size_t n4) {
    size_t i = (size_t)blockIdx.x * blockDim.x + threadIdx.x;
    size_t stride = (size_t)gridDim.x * blockDim.x;
    for (; i < n4; i += stride) {
        float4 v = ((const float4*)in)[i];
        __half2 h0 = __floats2half2_rn(v.x, v.y);
        __half2 h1 = __floats2half2_rn(v.z, v.w);
        ((__half2*)outp)[2 * i]     = h0;
        ((__half2*)outp)[2 * i + 1] = h1;
    }
}

// ---------------------------------------------------------------------------
// fp16 grouped GEMM + GELU.  CTA tile 128(m) x 256(n), BK=32, 5-stage cp.async.
// 512 threads = 16 warps: warpM = wid>>2 (x32 rows), warpN = wid&3 (x64 cols).
// A,B fp16 in smem; fragments via ldmatrix (A) / ldmatrix.trans (B).
// MODE 0: A = windowed g_xh[B,P,H] (K=4096, out g_h1h fp16)
// MODE 1: A = g_h1h [p][b][k]      (K=2048, out g_h2  fp32)
// W fp16 [P][K][N] row-major. C[p][b][n] = gelu(A@W + bias).
// ---------------------------------------------------------------------------
#define BM 128
#define BN 256
#define BK 32
#define ASTRH 40              // A smem row stride (halves): 80B rows, LDSM conflict-free
#define BSTRH 264             // B smem row stride (halves): 528B rows, LDSM conflict-free
#define ASZH (BM * ASTRH)     // 5120 halves
#define BSZH (BK * BSTRH)     // 8448 halves
#define STGB ((ASZH + BSZH) * 2)   // 27136 bytes / stage
#define NSTG 5
#define SMEM_BYTES (NSTG * STGB)   // 135680

template <int MODE>
__global__ void __launch_bounds__(512, 1)
gemm_f16_kernel(const __half* __restrict__ A, const __half* __restrict__ W,
                const float* __restrict__ bias, void* __restrict__ Cout,
                int K, int N) {
    extern __shared__ __half smem[];
    const uint32_t smem_u = (uint32_t)__cvta_generic_to_shared(smem);

    const int p    = blockIdx.z;
    const int bm   = blockIdx.y;
    const int bn   = blockIdx.x;
    const int tid  = threadIdx.x;
    const int wid  = tid >> 5;
    const int lane = tid & 31;
    const int warpM = wid >> 2;    // 0..3  (32 rows)
    const int warpN = wid & 3;     // 0..3  (64 cols)
    const int g  = lane >> 2;      // 0..7
    const int cc = lane & 3;       // 0..3

    // ldmatrix lane address components
    const int l7 = lane & 7;
    const int lb = (lane >> 3) & 1;
    const int lk = lane >> 4;
    // byte offsets within a stage
    const uint32_t aoff = ((warpM * 32 + lb * 8 + l7) * ASTRH + lk * 8) * 2;
    const uint32_t boff = (ASZH + (lb * 8 + l7) * BSTRH + warpN * 64 + lk * 8) * 2;

    float acc[2][8][4];
#pragma unroll
    for (int mf = 0; mf < 2; mf++)
#pragma unroll
        for (int nf = 0; nf < 8; nf++)
#pragma unroll
            for (int i = 0; i < 4; i++) acc[mf][nf][i] = 0.f;

    const __half* Wp = W + (size_t)p * K * N + (size_t)bn * BN;

    auto load_tiles = [&](int kt, int buf) {
        uint32_t sbase = smem_u + buf * STGB;
        // A: 128 rows x 32 halves = 512 x 16B chunks -> 1 per thread
        {
            int m  = tid >> 2;
            int kl = (tid & 3) * 8;
            int kg = kt * BK + kl;
            const __half* ga;
            int sz = 16;
            if (MODE == 0) {
                int half_ = (kg >= H_) ? 1 : 0;
                int pp    = p + half_;
                int kk    = kg - half_ * H_;
                if (pp >= P_) { pp = P_ - 1; sz = 0; }   // right-edge zero pad
                ga = A + ((size_t)(bm * BM + m) * P_ + pp) * H_ + kk;
            } else {
                ga = A + ((size_t)p * B_ + bm * BM + m) * (size_t)K + kg;
            }
            cp_async16(sbase + (m * ASTRH + kl) * 2, ga, sz);
        }
        // B: 32 rows x 256 halves = 1024 x 16B chunks -> 2 per thread
#pragma unroll
        for (int i = 0; i < 2; i++) {
            int c  = tid + i * 512;
            int kb = c >> 5;              // 0..31
            int nb = (c & 31) * 8;        // 0..248
            const __half* gb = Wp + (size_t)(kt * BK + kb) * N + nb;
            cp_async16(sbase + (ASZH + kb * BSTRH + nb) * 2, gb, 16);
        }
    };

    const int NKT = K / BK;
    const int pre = NKT < 4 ? NKT : 4;
    for (int i = 0; i < pre; i++) { load_tiles(i, i); cp_commit(); }

    for (int kt = 0; kt < NKT; ++kt) {
        if (kt + 4 < NKT) cp_wait<3>(); else cp_wait<0>();
        __syncthreads();
        if (kt + 4 < NKT) { load_tiles(kt + 4, (kt + 4) % NSTG); cp_commit(); }

        const uint32_t sbase = smem_u + (kt % NSTG) * STGB;
        const uint32_t aB = sbase + aoff;
        const uint32_t bB = sbase + boff;

#pragma unroll
        for (int ks = 0; ks < 2; ks++) {
            const uint32_t akk = aB + ks * 32;            // +16 halves along k
            const uint32_t bkk = bB + ks * (16 * BSTRH * 2);
            uint32_t a[2][4], b[4][4];
            ldsm4(akk,                 a[0][0], a[0][1], a[0][2], a[0][3]);
            ldsm4(akk + 16 * ASTRH * 2, a[1][0], a[1][1], a[1][2], a[1][3]);
#pragma unroll
            for (int np = 0; np < 4; np++)
                ldsm4t(bkk + np * 32, b[np][0], b[np][1], b[np][2], b[np][3]);
#pragma unroll
            for (int mf = 0; mf < 2; mf++)
#pragma unroll
                for (int np = 0; np < 4; np++) {
                    mma_f16(acc[mf][2 * np],     a[mf], &b[np][0]);
                    mma_f16(acc[mf][2 * np + 1], a[mf], &b[np][2]);
                }
        }
    }

    // Epilogue: bias + exact GELU.  MODE0 -> fp16 h1, MODE1 -> fp32 h2.
    const float* brow = bias + (size_t)p * N;
#pragma unroll
    for (int mf = 0; mf < 2; mf++) {
        int row0 = bm * BM + warpM * 32 + mf * 16 + g;
        size_t base0 = ((size_t)p * B_ + row0) * (size_t)N;
        size_t base8 = base0 + (size_t)8 * N;
#pragma unroll
        for (int nf = 0; nf < 8; nf++) {
            int n = bn * BN + warpN * 64 + nf * 8 + cc * 2;
            float bv0 = __ldg(brow + n);
            float bv1 = __ldg(brow + n + 1);
            float v0 = gelu_exact(acc[mf][nf][0] + bv0);
            float v1 = gelu_exact(acc[mf][nf][1] + bv1);
            float v2 = gelu_exact(acc[mf][nf][2] + bv0);
            float v3 = gelu_exact(acc[mf][nf][3] + bv1);
            if (MODE == 0) {
                __half* C = (__half*)Cout;
                *(__half2*)(C + base0 + n) = __floats2half2_rn(v0, v1);
                *(__half2*)(C + base8 + n) = __floats2half2_rn(v2, v3);
            } else {
                float* C = (float*)Cout;
                *(float2*)(C + base0 + n) = make_float2(v0, v1);
                *(float2*)(C + base8 + n) = make_float2(v2, v3);
            }
        }
    }
}

// ---------------------------------------------------------------------------
// Layer 3: out[b, p*4+o] = relu(sum_k h2[p][b][k] * W3[p][k][o] + b3[p][o])
// ---------------------------------------------------------------------------
__global__ void l3_kernel(const float* __restrict__ h2, const float* __restrict__ W3,
                          const float* __restrict__ b3, float* __restrict__ out) {
    int p = blockIdx.x, b = blockIdx.y;
    int tid = threadIdx.x;
    const float* hrow = h2 + ((size_t)p * B_ + b) * N2_;
    const float* w    = W3 + (size_t)p * N2_ * OUTP;

    float a0 = 0.f, a1 = 0.f, a2 = 0.f, a3 = 0.f;
    for (int k = tid; k < N2_; k += 128) {
        float hv = hrow[k];
        const float* wr = w + k * OUTP;
        a0 += hv * wr[0]; a1 += hv * wr[1]; a2 += hv * wr[2]; a3 += hv * wr[3];
    }
#pragma unroll
    for (int off = 16; off; off >>= 1) {
        a0 += __shfl_down_sync(0xffffffffu, a0, off);
        a1 += __shfl_down_sync(0xffffffffu, a1, off);
        a2 += __shfl_down_sync(0xffffffffu, a2, off);
        a3 += __shfl_down_sync(0xffffffffu, a3, off);
    }
    __shared__ float sred[4][4];
    int warp = tid >> 5, lane = tid & 31;
    if (lane == 0) {
        sred[warp][0] = a0; sred[warp][1] = a1; sred[warp][2] = a2; sred[warp][3] = a3;
    }
    __syncthreads();
    if (tid < 4) {
        float s = sred[0][tid] + sred[1][tid] + sred[2][tid] + sred[3][tid]
                + b3[p * OUTP + tid];
        out[(size_t)b * (P_ * OUTP) + p * OUTP + tid] = fmaxf(s, 0.f);
    }
}

// ---------------------------------------------------------------------------
extern "C" void kernel_launch(void* const* d_in, const int* in_sizes, int n_in,
                              void* d_out, int out_size) {
    const float* x  = (const float*)d_in[0];
    const float* W1 = (const float*)d_in[1];
    const float* b1 = (const float*)d_in[2];
    const float* W2 = (const float*)d_in[3];
    const float* b2 = (const float*)d_in[4];
    const float* W3 = (const float*)d_in[5];
    const float* b3 = (const float*)d_in[6];
    float* out = (float*)d_out;

    __half *xh, *w1h, *w2h, *h1h;
    float *h2;
    cudaGetSymbolAddress((void**)&xh,  g_xh);
    cudaGetSymbolAddress((void**)&w1h, g_w1h);
    cudaGetSymbolAddress((void**)&w2h, g_w2h);
    cudaGetSymbolAddress((void**)&h1h, g_h1h);
    cudaGetSymbolAddress((void**)&h2,  g_h2);

    cudaFuncSetAttribute(gemm_f16_kernel<0>,
                         cudaFuncAttributeMaxDynamicSharedMemorySize, SMEM_BYTES);
    cudaFuncSetAttribute(gemm_f16_kernel<1>,
                         cudaFuncAttributeMaxDynamicSharedMemorySize, SMEM_BYTES);

    // Prepass: fp32 -> fp16 converts (x, W1, W2)
    cvt_kernel<<<2048, 256>>>(x,  xh,  (size_t)B_ * P_ * H_ / 4);
    cvt_kernel<<<8192, 256>>>(W1, w1h, (size_t)P_ * K1_ * N1_ / 4);
    cvt_kernel<<<4096, 256>>>(W2, w2h, (size_t)P_ * K2_ * N2_ / 4);

    // Layer 1: [1024, 4096] @ [4096, 2048] per p, GELU -> fp16 h1
    gemm_f16_kernel<0><<<dim3(N1_ / BN, B_ / BM, P_), 512, SMEM_BYTES>>>(
        xh, w1h, b1, h1h, K1_, N1_);
    // Layer 2: [1024, 2048] @ [2048, 1024] per p, GELU -> fp32 h2
    gemm_f16_kernel<1><<<dim3(N2_ / BN, B_ / BM, P_), 512, SMEM_BYTES>>>(
        h1h, w2h, b2, h2, K2_, N2_);
    // Layer 3: tiny N=4 + ReLU
    l3_kernel<<<dim3(P_, B_), 128>>>(h2, W3, b3, out);
}

// round 6
// speedup vs baseline: 1.8746x; 1.0285x over previous
#include <cuda_runtime.h>
#include <cuda_fp16.h>
#include <cstdint>

// Problem constants
#define B_   1024
#define P_   24
#define H_   2048
#define K1_  4096   // H*R
#define N1_  2048   // H
#define K2_  2048
#define N2_  1024   // H/2
#define OUTP 4

// Scratch (allocation-free rule: __device__ globals)
__device__ __half g_xh [(size_t)B_ * P_ * H_];    // x   -> fp16   100MB
__device__ __half g_w1h[(size_t)P_ * K1_ * N1_];  // W1  -> fp16   402MB
__device__ __half g_w2h[(size_t)P_ * K2_ * N2_];  // W2  -> fp16   100MB
__device__ __half g_h1h[(size_t)P_ * B_ * N1_];   // layer1 out fp16
__device__ float  g_h2 [(size_t)P_ * B_ * N2_];   // layer2 out fp32

// ---------------------------------------------------------------------------
// helpers
// ---------------------------------------------------------------------------
__device__ __forceinline__ void mma_f16(float* c, const uint32_t* a, const uint32_t* b) {
    asm volatile(
        "mma.sync.aligned.m16n8k16.row.col.f32.f16.f16.f32 "
        "{%0,%1,%2,%3}, {%4,%5,%6,%7}, {%8,%9}, {%0,%1,%2,%3};"
        : "+f"(c[0]), "+f"(c[1]), "+f"(c[2]), "+f"(c[3])
        : "r"(a[0]), "r"(a[1]), "r"(a[2]), "r"(a[3]), "r"(b[0]), "r"(b[1]));
}

__device__ __forceinline__ void ldsm4(uint32_t addr, uint32_t* r) {
    asm volatile("ldmatrix.sync.aligned.m8n8.x4.shared.b16 {%0,%1,%2,%3}, [%4];"
                 : "=r"(r[0]), "=r"(r[1]), "=r"(r[2]), "=r"(r[3]) : "r"(addr));
}
__device__ __forceinline__ void ldsm4t(uint32_t addr, uint32_t* r) {
    asm volatile("ldmatrix.sync.aligned.m8n8.x4.trans.shared.b16 {%0,%1,%2,%3}, [%4];"
                 : "=r"(r[0]), "=r"(r[1]), "=r"(r[2]), "=r"(r[3]) : "r"(addr));
}

__device__ __forceinline__ void cp_async16(uint32_t smem_addr, const void* gptr, int src_size) {
    asm volatile("cp.async.cg.shared.global [%0], [%1], 16, %2;"
                 :: "r"(smem_addr), "l"(gptr), "r"(src_size));
}
__device__ __forceinline__ void cp_commit() {
    asm volatile("cp.async.commit_group;" ::: "memory");
}
template <int N>
__device__ __forceinline__ void cp_wait() {
    asm volatile("cp.async.wait_group %0;" :: "n"(N) : "memory");
}

__device__ __forceinline__ float gelu_exact(float v) {
    return 0.5f * v * (1.0f + erff(v * 0.7071067811865476f));
}

// ---------------------------------------------------------------------------
// Prepass: fp32 -> fp16 (RN) streaming convert
// ---------------------------------------------------------------------------
__global__ void cvt_kernel(const float* __restrict__ in, __half* __restrict__ outp, size_t n4) {
    size_t i = (size_t)blockIdx.x * blockDim.x + threadIdx.x;
    size_t stride = (size_t)gridDim.x * blockDim.x;
    for (; i < n4; i += stride) {
        float4 v = ((const float4*)in)[i];
        ((__half2*)outp)[2 * i]     = __floats2half2_rn(v.x, v.y);
        ((__half2*)outp)[2 * i + 1] = __floats2half2_rn(v.z, v.w);
    }
}

// ---------------------------------------------------------------------------
// fp16 grouped GEMM + GELU.  CTA tile 128(m) x 256(n), BK=64, 4-stage cp.async.
// 256 threads = 8 warps: warpM = wid>>2 (2, 64 rows), warpN = wid&3 (4, 64 cols).
// Warp tile 64x64, per-ks fragment double-buffering.
// MODE 0: A = windowed g_xh[B,P,H] (K=4096, out g_h1h fp16)
// MODE 1: A = g_h1h [p][b][k]      (K=2048, out g_h2  fp32)
// W fp16 [P][K][N] row-major. C[p][b][n] = gelu(A@W + bias).
// ---------------------------------------------------------------------------
#define BM 128
#define BN 256
#define BK 64
#define ASTRH 72              // A smem row stride (halves): 144B rows, LDSM conflict-free
#define BSTRH 264             // B smem row stride (halves): 528B rows, LDSM conflict-free
#define ASZB (BM * ASTRH * 2)          // 18432 B
#define BSZB (BK * BSTRH * 2)          // 33792 B
#define STGB (ASZB + BSZB)             // 52224 B / stage
#define NSTG 4
#define SMEM_BYTES (NSTG * STGB)       // 208896

template <int MODE>
__global__ void __launch_bounds__(256, 1)
gemm_f16_kernel(const __half* __restrict__ A, const __half* __restrict__ W,
                const float* __restrict__ bias, void* __restrict__ Cout,
                int K, int N) {
    extern __shared__ __half smem[];
    const uint32_t smem_u = (uint32_t)__cvta_generic_to_shared(smem);

    const int p    = blockIdx.z;
    const int bm   = blockIdx.y;
    const int bn   = blockIdx.x;
    const int tid  = threadIdx.x;
    const int wid  = tid >> 5;
    const int lane = tid & 31;
    const int warpM = wid >> 2;    // 0..1  (64 rows)
    const int warpN = wid & 3;     // 0..3  (64 cols)
    const int g  = lane >> 2;      // 0..7
    const int cc = lane & 3;       // 0..3

    // ldmatrix lane address components
    const int l7 = lane & 7;
    const int lb = (lane >> 3) & 1;
    const int lk = lane >> 4;
    const uint32_t aoff = ((warpM * 64 + lb * 8 + l7) * ASTRH + lk * 8) * 2;
    const uint32_t boff = ASZB + ((lb * 8 + l7) * BSTRH + warpN * 64 + lk * 8) * 2;

    float acc[4][8][4];
#pragma unroll
    for (int mf = 0; mf < 4; mf++)
#pragma unroll
        for (int nf = 0; nf < 8; nf++)
#pragma unroll
            for (int i = 0; i < 4; i++) acc[mf][nf][i] = 0.f;

    const __half* Wp = W + (size_t)p * K * N + (size_t)bn * BN;

    auto load_tiles = [&](int kt, int buf) {
        uint32_t sbase = smem_u + buf * STGB;
        // A: 128 rows x 64 halves = 1024 x 16B chunks -> 4 per thread
#pragma unroll
        for (int i = 0; i < 4; i++) {
            int c  = tid + i * 256;
            int m  = c >> 3;
            int kl = (c & 7) * 8;
            int kg = kt * BK + kl;
            const __half* ga;
            int sz = 16;
            if (MODE == 0) {
                int half_ = (kg >= H_) ? 1 : 0;
                int pp    = p + half_;
                int kk    = kg - half_ * H_;
                if (pp >= P_) { pp = P_ - 1; sz = 0; }   // right-edge zero pad
                ga = A + ((size_t)(bm * BM + m) * P_ + pp) * H_ + kk;
            } else {
                ga = A + ((size_t)p * B_ + bm * BM + m) * (size_t)K + kg;
            }
            cp_async16(sbase + (m * ASTRH + kl) * 2, ga, sz);
        }
        // B: 64 rows x 256 halves = 2048 x 16B chunks -> 8 per thread
#pragma unroll
        for (int i = 0; i < 8; i++) {
            int c  = tid + i * 256;
            int kb = c >> 5;              // 0..63
            int nb = (c & 31) * 8;        // 0..248
            const __half* gb = Wp + (size_t)(kt * BK + kb) * N + nb;
            cp_async16(sbase + ASZB + (kb * BSTRH + nb) * 2, gb, 16);
        }
    };

    const int NKT = K / BK;          // >= 32
    load_tiles(0, 0); cp_commit();
    load_tiles(1, 1); cp_commit();
    load_tiles(2, 2); cp_commit();

    uint32_t a[2][4][4], b[2][4][4];

    for (int kt = 0; kt < NKT; ++kt) {
        cp_wait<2>();                 // invariant: 3 groups pending before wait
        __syncthreads();
        if (kt + 3 < NKT) load_tiles(kt + 3, (kt + 3) & 3);
        cp_commit();                  // possibly-empty group keeps invariant

        const uint32_t sbase = smem_u + (kt & 3) * STGB;
        const uint32_t aB = sbase + aoff;
        const uint32_t bB = sbase + boff;

        // prefetch ks=0 fragments
#pragma unroll
        for (int f = 0; f < 4; f++) ldsm4(aB + f * (16 * ASTRH * 2), a[0][f]);
#pragma unroll
        for (int nf = 0; nf < 4; nf++) ldsm4t(bB + nf * 32, b[0][nf]);

#pragma unroll
        for (int ks = 0; ks < 4; ks++) {
            const int cb = ks & 1;
            if (ks < 3) {
                const int nb2 = cb ^ 1;
                const uint32_t akk = aB + (ks + 1) * 32;
                const uint32_t bkk = bB + (ks + 1) * (16 * BSTRH * 2);
#pragma unroll
                for (int f = 0; f < 4; f++) ldsm4(akk + f * (16 * ASTRH * 2), a[nb2][f]);
#pragma unroll
                for (int nf = 0; nf < 4; nf++) ldsm4t(bkk + nf * 32, b[nb2][nf]);
            }
#pragma unroll
            for (int mf = 0; mf < 4; mf++)
#pragma unroll
                for (int nf = 0; nf < 4; nf++) {
                    mma_f16(acc[mf][2 * nf],     a[cb][mf], &b[cb][nf][0]);
                    mma_f16(acc[mf][2 * nf + 1], a[cb][mf], &b[cb][nf][2]);
                }
        }
    }

    // Epilogue: bias + exact GELU.  MODE0 -> fp16 h1, MODE1 -> fp32 h2.
    const float* brow = bias + (size_t)p * N;
#pragma unroll
    for (int mf = 0; mf < 4; mf++) {
        int row0 = bm * BM + warpM * 64 + mf * 16 + g;
        size_t base0 = ((size_t)p * B_ + row0) * (size_t)N;
        size_t base8 = base0 + (size_t)8 * N;
#pragma unroll
        for (int nf = 0; nf < 8; nf++) {
            int n = bn * BN + warpN * 64 + nf * 8 + cc * 2;
            float bv0 = __ldg(brow + n);
            float bv1 = __ldg(brow + n + 1);
            float v0 = gelu_exact(acc[mf][nf][0] + bv0);
            float v1 = gelu_exact(acc[mf][nf][1] + bv1);
            float v2 = gelu_exact(acc[mf][nf][2] + bv0);
            float v3 = gelu_exact(acc[mf][nf][3] + bv1);
            if (MODE == 0) {
                __half* C = (__half*)Cout;
                *(__half2*)(C + base0 + n) = __floats2half2_rn(v0, v1);
                *(__half2*)(C + base8 + n) = __floats2half2_rn(v2, v3);
            } else {
                float* C = (float*)Cout;
                *(float2*)(C + base0 + n) = make_float2(v0, v1);
                *(float2*)(C + base8 + n) = make_float2(v2, v3);
            }
        }
    }
}

// ---------------------------------------------------------------------------
// Layer 3: out[b, p*4+o] = relu(sum_k h2[p][b][k] * W3[p][k][o] + b3[p][o])
// ---------------------------------------------------------------------------
__global__ void l3_kernel(const float* __restrict__ h2, const float* __restrict__ W3,
                          const float* __restrict__ b3, float* __restrict__ out) {
    int p = blockIdx.x, b = blockIdx.y;
    int tid = threadIdx.x;
    const float* hrow = h2 + ((size_t)p * B_ + b) * N2_;
    const float* w    = W3 + (size_t)p * N2_ * OUTP;

    float a0 = 0.f, a1 = 0.f, a2 = 0.f, a3 = 0.f;
    for (int k = tid; k < N2_; k += 128) {
        float hv = hrow[k];
        const float* wr = w + k * OUTP;
        a0 += hv * wr[0]; a1 += hv * wr[1]; a2 += hv * wr[2]; a3 += hv * wr[3];
    }
#pragma unroll
    for (int off = 16; off; off >>= 1) {
        a0 += __shfl_down_sync(0xffffffffu, a0, off);
        a1 += __shfl_down_sync(0xffffffffu, a1, off);
        a2 += __shfl_down_sync(0xffffffffu, a2, off);
        a3 += __shfl_down_sync(0xffffffffu, a3, off);
    }
    __shared__ float sred[4][4];
    int warp = tid >> 5, lane = tid & 31;
    if (lane == 0) {
        sred[warp][0] = a0; sred[warp][1] = a1; sred[warp][2] = a2; sred[warp][3] = a3;
    }
    __syncthreads();
    if (tid < 4) {
        float s = sred[0][tid] + sred[1][tid] + sred[2][tid] + sred[3][tid]
                + b3[p * OUTP + tid];
        out[(size_t)b * (P_ * OUTP) + p * OUTP + tid] = fmaxf(s, 0.f);
    }
}

// ---------------------------------------------------------------------------
extern "C" void kernel_launch(void* const* d_in, const int* in_sizes, int n_in,
                              void* d_out, int out_size) {
    const float* x  = (const float*)d_in[0];
    const float* W1 = (const float*)d_in[1];
    const float* b1 = (const float*)d_in[2];
    const float* W2 = (const float*)d_in[3];
    const float* b2 = (const float*)d_in[4];
    const float* W3 = (const float*)d_in[5];
    const float* b3 = (const float*)d_in[6];
    float* out = (float*)d_out;

    __half *xh, *w1h, *w2h, *h1h;
    float *h2;
    cudaGetSymbolAddress((void**)&xh,  g_xh);
    cudaGetSymbolAddress((void**)&w1h, g_w1h);
    cudaGetSymbolAddress((void**)&w2h, g_w2h);
    cudaGetSymbolAddress((void**)&h1h, g_h1h);
    cudaGetSymbolAddress((void**)&h2,  g_h2);

    cudaFuncSetAttribute(gemm_f16_kernel<0>,
                         cudaFuncAttributeMaxDynamicSharedMemorySize, SMEM_BYTES);
    cudaFuncSetAttribute(gemm_f16_kernel<1>,
                         cudaFuncAttributeMaxDynamicSharedMemorySize, SMEM_BYTES);

    // Prepass: fp32 -> fp16 converts (x, W1, W2)
    cvt_kernel<<<2048, 256>>>(x,  xh,  (size_t)B_ * P_ * H_ / 4);
    cvt_kernel<<<8192, 256>>>(W1, w1h, (size_t)P_ * K1_ * N1_ / 4);
    cvt_kernel<<<4096, 256>>>(W2, w2h, (size_t)P_ * K2_ * N2_ / 4);

    // Layer 1: [1024, 4096] @ [4096, 2048] per p, GELU -> fp16 h1
    gemm_f16_kernel<0><<<dim3(N1_ / BN, B_ / BM, P_), 256, SMEM_BYTES>>>(
        xh, w1h, b1, h1h, K1_, N1_);
    // Layer 2: [1024, 2048] @ [2048, 1024] per p, GELU -> fp32 h2
    gemm_f16_kernel<1><<<dim3(N2_ / BN, B_ / BM, P_), 256, SMEM_BYTES>>>(
        h1h, w2h, b2, h2, K2_, N2_);
    // Layer 3: tiny N=4 + ReLU
    l3_kernel<<<dim3(P_, B_), 128>>>(h2, W3, b3, out);
}